// round 11
// baseline (speedup 1.0000x reference)
#include <cuda_runtime.h>
#include <stdint.h>

// Problem constants (fixed: v is [32, 2, 512, 512] fp32)
#define NB 32
#define HH 512
#define WW 512
#define HW (HH * WW)          // 262144 = 2^18
#define QTR (HW / 4)          // 65536  = 2^16
#define TOTAL (NB * HW)       // 8388608
#define NO_STEPS 16
#define SCALE 0x1p-16f        // 1 / 2^16

// Ping-pong scratch: warp field interleaved [n][y][x] -> float2(ch0, ch1).
__device__ float2 g_bufA[TOTAL];
__device__ float2 g_bufB[TOTAL];

// ---------------------------------------------------------------------------
// Bilinear sample, border clamp, align_corners=False, interleaved float2 plane.
// Coordinate math bit-identical to reference; power-of-2 muls exact.
// ---------------------------------------------------------------------------
__device__ __forceinline__ float2 sample_plane(const float2* __restrict__ plane,
                                               float sx, float sy) {
    float ix = fminf(fmaxf(((sx + 1.0f) * (float)WW - 1.0f) * 0.5f, 0.0f), (float)(WW - 1));
    float iy = fminf(fmaxf(((sy + 1.0f) * (float)HH - 1.0f) * 0.5f, 0.0f), (float)(HH - 1));
    float fx0 = floorf(ix);
    float fy0 = floorf(iy);
    int x0 = (int)fx0, y0 = (int)fy0;
    int x1 = min(x0 + 1, WW - 1);
    int y1 = min(y0 + 1, HH - 1);
    float wx = ix - fx0, wy = iy - fy0;
    float2 a = __ldg(plane + y0 * WW + x0);
    float2 b = __ldg(plane + y0 * WW + x1);
    float2 c = __ldg(plane + y1 * WW + x0);
    float2 d = __ldg(plane + y1 * WW + x1);
    float owx = 1.0f - wx, owy = 1.0f - wy;
    float2 top, bot, r;
    top.x = a.x * owx + b.x * wx;  top.y = a.y * owx + b.y * wx;
    bot.x = c.x * owx + d.x * wx;  bot.y = c.y * owx + d.y * wx;
    r.x = top.x * owy + bot.x * wy;
    r.y = top.y * owy + bot.y * wy;
    return r;
}

// Bilinear over NCHW v planes with 2^-16 scale folded into every tap.
__device__ __forceinline__ float2 sample_v(const float* __restrict__ p0,
                                           const float* __restrict__ p1,
                                           float sx, float sy) {
    float ix = fminf(fmaxf(((sx + 1.0f) * (float)WW - 1.0f) * 0.5f, 0.0f), (float)(WW - 1));
    float iy = fminf(fmaxf(((sy + 1.0f) * (float)HH - 1.0f) * 0.5f, 0.0f), (float)(HH - 1));
    float fx0 = floorf(ix);
    float fy0 = floorf(iy);
    int x0 = (int)fx0, y0 = (int)fy0;
    int x1 = min(x0 + 1, WW - 1);
    int y1 = min(y0 + 1, HH - 1);
    float wx = ix - fx0, wy = iy - fy0;
    int i00 = y0 * WW + x0, i01 = y0 * WW + x1, i10 = y1 * WW + x0, i11 = y1 * WW + x1;
    float owx = 1.0f - wx, owy = 1.0f - wy;
    float2 r;
    {
        float a = __ldg(p0 + i00) * SCALE, b = __ldg(p0 + i01) * SCALE;
        float c = __ldg(p0 + i10) * SCALE, d = __ldg(p0 + i11) * SCALE;
        r.x = (a * owx + b * wx) * owy + (c * owx + d * wx) * wy;
    }
    {
        float a = __ldg(p1 + i00) * SCALE, b = __ldg(p1 + i01) * SCALE;
        float c = __ldg(p1 + i10) * SCALE, d = __ldg(p1 + i11) * SCALE;
        r.y = (a * owx + b * wx) * owy + (c * owx + d * wx) * wy;
    }
    return r;
}

// ---------------------------------------------------------------------------
// Step 1 fused with init: wf0 = v*2^-16 ; out = wf0 + sample(wf0, id+wf0)
// Each thread: pixels lp + j*QTR (j=0..3) of one image.
// ---------------------------------------------------------------------------
__global__ __launch_bounds__(256)
void svf_first(const float* __restrict__ v, const float2* __restrict__ ig,
               float2* __restrict__ dst) {
    int t = blockIdx.x * blockDim.x + threadIdx.x;   // TOTAL/4 threads
    int lp  = t & (QTR - 1);
    int img = t >> 16;
    const float* p0 = v + (size_t)img * 2 * HW;      // ch0 plane
    const float* p1 = p0 + HW;                       // ch1 plane
    float2* d = dst + ((size_t)img << 18);
    #pragma unroll
    for (int j = 0; j < 4; ++j) {
        int l = lp + j * QTR;
        float sx = __ldg(p0 + l) * SCALE;
        float sy = __ldg(p1 + l) * SCALE;
        float2 g = __ldg(ig + l);
        float2 sm = sample_v(p0, p1, g.x + sx, g.y + sy);
        float2 o; o.x = sx + sm.x; o.y = sy + sm.y;
        d[l] = o;
    }
}

// ---------------------------------------------------------------------------
// Middle step: wf' = wf + sample(wf, id + wf). 4 far-apart px per thread.
// ---------------------------------------------------------------------------
__global__ __launch_bounds__(256)
void svf_step(const float2* __restrict__ src, const float2* __restrict__ ig,
              float2* __restrict__ dst) {
    int t = blockIdx.x * blockDim.x + threadIdx.x;
    int lp  = t & (QTR - 1);
    int img = t >> 16;
    const float2* plane = src + ((size_t)img << 18);
    float2* d = dst + ((size_t)img << 18);

    // Load all centers and grids up front -> maximal overlap of tap loads.
    float2 s0 = plane[lp];
    float2 s1 = plane[lp + QTR];
    float2 s2 = plane[lp + 2 * QTR];
    float2 s3 = plane[lp + 3 * QTR];
    float2 g0 = __ldg(ig + lp);
    float2 g1 = __ldg(ig + lp + QTR);
    float2 g2 = __ldg(ig + lp + 2 * QTR);
    float2 g3 = __ldg(ig + lp + 3 * QTR);

    float2 sm0 = sample_plane(plane, g0.x + s0.x, g0.y + s0.y);
    float2 sm1 = sample_plane(plane, g1.x + s1.x, g1.y + s1.y);
    float2 sm2 = sample_plane(plane, g2.x + s2.x, g2.y + s2.y);
    float2 sm3 = sample_plane(plane, g3.x + s3.x, g3.y + s3.y);

    float2 o0; o0.x = s0.x + sm0.x; o0.y = s0.y + sm0.y;
    float2 o1; o1.x = s1.x + sm1.x; o1.y = s1.y + sm1.y;
    float2 o2; o2.x = s2.x + sm2.x; o2.y = s2.y + sm2.y;
    float2 o3; o3.x = s3.x + sm3.x; o3.y = s3.y + sm3.y;
    d[lp]           = o0;
    d[lp + QTR]     = o1;
    d[lp + 2 * QTR] = o2;
    d[lp + 3 * QTR] = o3;
}

// ---------------------------------------------------------------------------
// Last step fused with epilogue: writes transformation & warp_field (NCHW).
// d_out layout: [transformation (N,2,H,W) | warp_field (N,2,H,W)]
// ---------------------------------------------------------------------------
__global__ __launch_bounds__(256)
void svf_last(const float2* __restrict__ src, const float2* __restrict__ ig,
              float* __restrict__ out) {
    int t = blockIdx.x * blockDim.x + threadIdx.x;
    int lp  = t & (QTR - 1);
    int img = t >> 16;
    const float2* plane = src + ((size_t)img << 18);
    const size_t half = (size_t)NB * 2 * HW;
    size_t ch0 = ((size_t)img * 2) * HW;
    #pragma unroll
    for (int j = 0; j < 4; ++j) {
        int l = lp + j * QTR;
        float2 s = plane[l];
        float2 g = __ldg(ig + l);
        float2 sm = sample_plane(plane, g.x + s.x, g.y + s.y);
        float wfx = s.x + sm.x, wfy = s.y + sm.y;
        size_t base = ch0 + l;
        out[base]             = wfx + g.x;   // transformation ch0
        out[base + HW]        = wfy + g.y;   // transformation ch1
        out[half + base]      = wfx;         // warp_field ch0
        out[half + base + HW] = wfy;         // warp_field ch1
    }
}

extern "C" void kernel_launch(void* const* d_in, const int* in_sizes, int n_in,
                              void* d_out, int out_size) {
    const float*  v  = (const float*)d_in[0];
    const float2* ig = (const float2*)d_in[1];   // [1,H,W,2] contiguous
    float* out = (float*)d_out;

    float2* bufA = nullptr;
    float2* bufB = nullptr;
    cudaGetSymbolAddress((void**)&bufA, g_bufA);
    cudaGetSymbolAddress((void**)&bufB, g_bufB);

    const int threads = 256;
    const int blocks = (TOTAL / 4) / threads;    // 8192

    // step 1: v -> bufA
    svf_first<<<blocks, threads>>>(v, ig, bufA);

    // steps 2..15: ping-pong
    float2* cur = bufA;
    float2* nxt = bufB;
    for (int k = 2; k <= NO_STEPS - 1; ++k) {
        svf_step<<<blocks, threads>>>(cur, ig, nxt);
        float2* tswap = cur; cur = nxt; nxt = tswap;
    }

    // step 16: cur -> d_out
    svf_last<<<blocks, threads>>>(cur, ig, out);
}